// round 1
// baseline (speedup 1.0000x reference)
#include <cuda_runtime.h>
#include <cstdint>

// ---------------- constants ----------------
#define Bb   256
#define Pp   192
#define DD   768     // DV == DT
#define EE   256
#define AA   8
#define KK   4

// ---------------- scratch (static device globals; no allocations) --------
__device__ float g_pat[(size_t)Bb * Pp * EE];   // 48 MB (normalized in place)
__device__ float g_att[(size_t)Bb * AA * EE];   // 2 MB
__device__ float g_sim[(size_t)Bb * AA * Pp];   // 1.5 MB

// ---------------- generic tiled fp32 GEMM: C[M,256] = A'[M,768] @ W[768,256] + b
// A row remap: global_row(m) = (m / rpb) * pitch + base + (m % rpb)
//   ve : rpb=1,   pitch=193, base=0   (visual_feature[:,0,:])
//   te : rpb=1,   pitch=1,   base=0
//   pat: rpb=192, pitch=193, base=1   (visual_feature[:,1:,:])
//   att: rpb=1,   pitch=1,   base=0
#define BM 64
#define BN 64
#define BK 16

__global__ __launch_bounds__(256, 4)
void gemm_bias(const float* __restrict__ A, const float* __restrict__ W,
               const float* __restrict__ bias, float* __restrict__ C,
               int rpb, int pitch, int base)
{
    __shared__ float As[BK][BM + 1];
    __shared__ float Ws[BK][BN];

    const int t  = threadIdx.x;           // 256 threads
    const int bm = blockIdx.x;
    const int bn = blockIdx.y;

    // A-tile load map: thread -> (row ra, col4 ca), covers 64x16
    const int ra = t >> 2;
    const int ca = (t & 3) * 4;
    const int gm = bm * BM + ra;
    const int grow = (gm / rpb) * pitch + base + (gm % rpb);
    const float* Arow = A + (size_t)grow * DD + ca;

    // W-tile load map: thread -> (row rw, col4 cw), covers 16x64
    const int rw = t >> 4;
    const int cw = (t & 15) * 4;
    const float* Wptr = W + (size_t)rw * EE + bn * BN + cw;

    const int tm = (t >> 4) * 4;
    const int tn = (t & 15) * 4;

    float acc[4][4] = {};

    for (int k0 = 0; k0 < DD; k0 += BK) {
        float4 av = *(const float4*)(Arow + k0);
        float4 wv = *(const float4*)(Wptr + (size_t)k0 * EE);
        __syncthreads();
        As[ca + 0][ra] = av.x;
        As[ca + 1][ra] = av.y;
        As[ca + 2][ra] = av.z;
        As[ca + 3][ra] = av.w;
        *(float4*)&Ws[rw][cw] = wv;
        __syncthreads();
#pragma unroll
        for (int k = 0; k < BK; k++) {
            float a0 = As[k][tm + 0], a1 = As[k][tm + 1];
            float a2 = As[k][tm + 2], a3 = As[k][tm + 3];
            float w0 = Ws[k][tn + 0], w1 = Ws[k][tn + 1];
            float w2 = Ws[k][tn + 2], w3 = Ws[k][tn + 3];
            acc[0][0] += a0 * w0; acc[0][1] += a0 * w1; acc[0][2] += a0 * w2; acc[0][3] += a0 * w3;
            acc[1][0] += a1 * w0; acc[1][1] += a1 * w1; acc[1][2] += a1 * w2; acc[1][3] += a1 * w3;
            acc[2][0] += a2 * w0; acc[2][1] += a2 * w1; acc[2][2] += a2 * w2; acc[2][3] += a2 * w3;
            acc[3][0] += a3 * w0; acc[3][1] += a3 * w1; acc[3][2] += a3 * w2; acc[3][3] += a3 * w3;
        }
    }

    const float4 bb = *(const float4*)(bias + bn * BN + tn);
#pragma unroll
    for (int i = 0; i < 4; i++) {
        float4 o;
        o.x = acc[i][0] + bb.x;
        o.y = acc[i][1] + bb.y;
        o.z = acc[i][2] + bb.z;
        o.w = acc[i][3] + bb.w;
        *(float4*)&C[(size_t)(bm * BM + tm + i) * EE + bn * BN + tn] = o;
    }
}

// ---------------- per-row L2 normalize (rows of length 256), one warp per row
__global__ __launch_bounds__(256)
void l2norm_rows(float* __restrict__ X, int nrows)
{
    const int warp = (blockIdx.x * blockDim.x + threadIdx.x) >> 5;
    const int lane = threadIdx.x & 31;
    if (warp >= nrows) return;
    float* row = X + (size_t)warp * EE;
    float v[8];
    float ss = 0.f;
#pragma unroll
    for (int i = 0; i < 8; i++) { v[i] = row[lane + 32 * i]; ss += v[i] * v[i]; }
#pragma unroll
    for (int o = 16; o; o >>= 1) ss += __shfl_xor_sync(0xffffffffu, ss, o);
    const float inv = 1.f / fmaxf(sqrtf(ss), 1e-12f);
#pragma unroll
    for (int i = 0; i < 8; i++) row[lane + 32 * i] = v[i] * inv;
}

// ---------------- sim[b,a,p] = att[b,a,:] . pat[b,p,:]  (one block per batch)
__global__ __launch_bounds__(256)
void sim_kernel(const float* __restrict__ pat, const float* __restrict__ att,
                float* __restrict__ sim)
{
    const int b = blockIdx.x;
    __shared__ float s_att[AA * EE];
    const int t = threadIdx.x;
    for (int i = t; i < AA * EE; i += 256)
        s_att[i] = att[(size_t)b * AA * EE + i];
    __syncthreads();

    const int warp = t >> 5, lane = t & 31;
    for (int p = warp; p < Pp; p += 8) {
        const float* pr = pat + ((size_t)b * Pp + p) * EE;
        float acc[AA] = {};
        for (int e = lane; e < EE; e += 32) {
            const float v = pr[e];
#pragma unroll
            for (int a = 0; a < AA; a++) acc[a] += v * s_att[a * EE + e];
        }
#pragma unroll
        for (int a = 0; a < AA; a++)
#pragma unroll
            for (int o = 16; o; o >>= 1) acc[a] += __shfl_xor_sync(0xffffffffu, acc[a], o);
        if (lane == 0) {
#pragma unroll
            for (int a = 0; a < AA; a++)
                sim[(size_t)b * AA * Pp + a * Pp + p] = acc[a];
        }
    }
}

// ---------------- Jonker-Volgenant Hungarian, K rounds with masking.
// One warp per batch. Minimizes cost = -sim (i.e. maximizes sim).
__global__ __launch_bounds__(32)
void hungarian_kernel(const float* __restrict__ simg, float* __restrict__ out)
{
    const int b = blockIdx.x;
    const int lane = threadIdx.x;
    const int M = Pp;                 // 192 columns
    const float FINF = 1e30f;

    __shared__ float cost[AA][Pp];
    __shared__ float vsh[Pp + 1];
    __shared__ float minv[Pp + 1];
    __shared__ float ush[AA + 1];
    __shared__ int   psh[Pp + 1];
    __shared__ int   waysh[Pp + 1];
    __shared__ int   usedsh[Pp + 1];

    for (int idx = lane; idx < AA * Pp; idx += 32)
        cost[idx / Pp][idx % Pp] = -simg[(size_t)b * AA * Pp + idx];
    __syncwarp();

    float total = 0.f;

    for (int round = 0; round < KK; round++) {
        for (int j = lane; j <= M; j += 32) { vsh[j] = 0.f; psh[j] = 0; }
        if (lane < AA + 1) ush[lane] = 0.f;
        __syncwarp();

        for (int i = 1; i <= AA; i++) {
            if (lane == 0) psh[0] = i;
            for (int j = lane; j <= M; j += 32) { minv[j] = FINF; usedsh[j] = 0; }
            __syncwarp();
            int j0 = 0;
            while (true) {
                if (lane == 0) usedsh[j0] = 1;
                __syncwarp();
                const int i0 = psh[j0];
                const float ui0 = ush[i0];

                float best = FINF;
                int bestj = 1 << 20;
                for (int j = lane + 1; j <= M; j += 32) {
                    if (!usedsh[j]) {
                        float cur = cost[i0 - 1][j - 1] - ui0 - vsh[j];
                        if (cur < minv[j]) { minv[j] = cur; waysh[j] = j0; }
                        const float mv = minv[j];
                        if (mv < best || (mv == best && j < bestj)) { best = mv; bestj = j; }
                    }
                }
                __syncwarp();
                // full-warp min reduction with smallest-index tiebreak (matches np.argmin)
#pragma unroll
                for (int o = 16; o; o >>= 1) {
                    float ob = __shfl_xor_sync(0xffffffffu, best, o);
                    int   oj = __shfl_xor_sync(0xffffffffu, bestj, o);
                    if (ob < best || (ob == best && oj < bestj)) { best = ob; bestj = oj; }
                }
                const float delta = best;
                const int j1 = bestj;

                for (int j = lane; j <= M; j += 32) {
                    if (usedsh[j]) { ush[psh[j]] += delta; vsh[j] -= delta; }
                    else           { minv[j] -= delta; }
                }
                __syncwarp();
                j0 = j1;
                if (psh[j0] == 0) break;
            }
            if (lane == 0) {
                int jc = j0;
                while (jc) { int jn = waysh[jc]; psh[jc] = psh[jn]; jc = jn; }
            }
            __syncwarp();
        }

        // collect matched values (still unmasked this round) and mask them
        for (int j = lane + 1; j <= M; j += 32) {
            const int r = psh[j];
            if (r) {
                total += -cost[r - 1][j - 1];
                cost[r - 1][j - 1] = 100.f;   // == -(-100)
            }
        }
        __syncwarp();
    }

#pragma unroll
    for (int o = 16; o; o >>= 1) total += __shfl_xor_sync(0xffffffffu, total, o);
    if (lane == 0) out[b] = total * (1.f / (KK * AA));
}

// ---------------- launch ----------------
extern "C" void kernel_launch(void* const* d_in, const int* in_sizes, int n_in,
                              void* d_out, int out_size)
{
    const float* vf = (const float*)d_in[0];   // [256,193,768]
    const float* tf = (const float*)d_in[1];   // [256,768]
    const float* af = (const float*)d_in[2];   // [2048,768]
    // d_in[3] = att_nums (all == A, unused)
    const float* Wv = (const float*)d_in[4];
    const float* bv = (const float*)d_in[5];
    const float* Wt = (const float*)d_in[6];
    const float* bt = (const float*)d_in[7];
    const float* Wp = (const float*)d_in[8];
    const float* bp = (const float*)d_in[9];
    const float* Wa = (const float*)d_in[10];
    const float* ba = (const float*)d_in[11];

    float* out = (float*)d_out;
    float* ve = out;                 // [256,256]
    float* te = out + Bb * EE;       // [256,256]
    float* ls = out + 2 * Bb * EE;   // [256]

    float *gpat, *gatt, *gsim;
    cudaGetSymbolAddress((void**)&gpat, g_pat);
    cudaGetSymbolAddress((void**)&gatt, g_att);
    cudaGetSymbolAddress((void**)&gsim, g_sim);

    dim3 blk(256);
    // visual_embed / textual_embed straight into d_out
    gemm_bias<<<dim3(Bb / BM, EE / BN), blk>>>(vf, Wv, bv, ve, 1, 193, 0);
    gemm_bias<<<dim3(Bb / BM, EE / BN), blk>>>(tf, Wt, bt, te, 1, 1, 0);
    // patch embed (big GEMM) and attribute embed
    gemm_bias<<<dim3((Bb * Pp) / BM, EE / BN), blk>>>(vf, Wp, bp, gpat, Pp, 193, 1);
    gemm_bias<<<dim3((Bb * AA) / BM, EE / BN), blk>>>(af, Wa, ba, gatt, 1, 1, 0);
    // normalize
    l2norm_rows<<<(Bb * Pp) / 8, 256>>>(gpat, Bb * Pp);
    l2norm_rows<<<(Bb * AA) / 8, 256>>>(gatt, Bb * AA);
    // similarity
    sim_kernel<<<Bb, 256>>>(gpat, gatt, gsim);
    // K-round masked Hungarian -> local_similarity
    hungarian_kernel<<<Bb, 32>>>(gsim, ls);
}

// round 3
// speedup vs baseline: 2.3022x; 2.3022x over previous
#include <cuda_runtime.h>
#include <cuda_bf16.h>
#include <cstdint>

// ---------------- constants ----------------
#define Bb   256
#define Pp   192
#define DD   768
#define EE   256
#define AA   8
#define KK   4

#define M_TOTAL   51712          // 256(ve) + 256(te) + 49152(pat) + 2048(att)
#define SEG1      256
#define SEG2      512
#define SEG3      49664
#define MTILES    404            // M_TOTAL / 128
#define BKC       32             // K per chunk (bf16 elems)
#define NCH       24             // 768 / 32

// SMEM: 4 operands (AH, AL, BH, BL), each 128 rows x 80 bytes, double buffered
#define ROWB    80
#define OPSZ    (128 * ROWB)     // 10240
#define OFF_AH  0
#define OFF_AL  (OPSZ)
#define OFF_BH  (2 * OPSZ)
#define OFF_BL  (3 * OPSZ)
#define STAGESZ (4 * OPSZ)       // 40960
#define DYNSZ   (2 * STAGESZ)    // 81920

// ---------------- scratch ----------------
__device__ float g_pat[(size_t)Bb * Pp * EE];   // unnormalized patch embed
__device__ float g_att[(size_t)Bb * AA * EE];   // unnormalized att embed
__device__ float g_sim[(size_t)Bb * AA * Pp];
__device__ __nv_bfloat16 g_wt_hi[4][256 * 768]; // W^T hi bf16, [N][K]
__device__ __nv_bfloat16 g_wt_lo[4][256 * 768]; // W^T lo bf16

// ---------------- PTX helpers ----------------
static __device__ __forceinline__ uint32_t smem_u32(const void* p) {
    uint32_t a;
    asm("{ .reg .u64 t; cvta.to.shared.u64 t, %1; cvt.u32.u64 %0, t; }"
        : "=r"(a) : "l"(p));
    return a;
}

#define LDSM4(r, addr) \
    asm volatile("ldmatrix.sync.aligned.m8n8.x4.shared.b16 {%0,%1,%2,%3}, [%4];" \
        : "=r"((r)[0]), "=r"((r)[1]), "=r"((r)[2]), "=r"((r)[3]) : "r"(addr))

#define MMA(c, a, b0, b1) \
    asm volatile("mma.sync.aligned.m16n8k16.row.col.f32.bf16.bf16.f32 " \
        "{%0,%1,%2,%3}, {%4,%5,%6,%7}, {%8,%9}, {%0,%1,%2,%3};" \
        : "+f"((c)[0]), "+f"((c)[1]), "+f"((c)[2]), "+f"((c)[3]) \
        : "r"((a)[0]), "r"((a)[1]), "r"((a)[2]), "r"((a)[3]), "r"(b0), "r"(b1))

static __device__ __forceinline__ void cp16(uint32_t s, const void* g) {
    asm volatile("cp.async.cg.shared.global [%0], [%1], 16;" :: "r"(s), "l"(g));
}
#define CP_COMMIT() asm volatile("cp.async.commit_group;" ::: "memory")
#define CP_WAIT0()  asm volatile("cp.async.wait_group 0;" ::: "memory")

// ---------------- W transpose + bf16 hi/lo split ----------------
__global__ void wsplit_kernel(const float* __restrict__ W0, const float* __restrict__ W1,
                              const float* __restrict__ W2, const float* __restrict__ W3)
{
    const int z = blockIdx.z;
    const float* W = (z == 0) ? W0 : (z == 1) ? W1 : (z == 2) ? W2 : W3;
    __shared__ float tile[32][33];
    const int tx = threadIdx.x, ty = threadIdx.y;
    const int k0 = blockIdx.x * 32, n0 = blockIdx.y * 32;
#pragma unroll
    for (int i = 0; i < 4; i++)
        tile[ty + 8 * i][tx] = W[(size_t)(k0 + ty + 8 * i) * 256 + n0 + tx];
    __syncthreads();
#pragma unroll
    for (int i = 0; i < 4; i++) {
        const float v = tile[tx][ty + 8 * i];
        const __nv_bfloat16 hi = __float2bfloat16(v);
        const __nv_bfloat16 lo = __float2bfloat16(v - __bfloat162float(hi));
        const size_t o = (size_t)(n0 + ty + 8 * i) * 768 + k0 + tx;
        g_wt_hi[z][o] = hi;
        g_wt_lo[z][o] = lo;
    }
}

// ---------------- fused HMMA GEMM: C[m,256] = A[m,768] @ W + bias ----------
__global__ __launch_bounds__(256, 1)
void gemm_mma(const float* __restrict__ vf, const float* __restrict__ tf,
              const float* __restrict__ af,
              const float* __restrict__ bv, const float* __restrict__ bt,
              const float* __restrict__ bp, const float* __restrict__ ba,
              float* __restrict__ out)
{
    extern __shared__ char dynsm[];
    __shared__ int sRowOff[128];

    const int t = threadIdx.x;
    const int warp = t >> 5;
    const int lane = t & 31;
    const int m0 = blockIdx.x * 128;
    const int bn = blockIdx.y;           // 0 or 1 (N halves)

    const int seg = (m0 < SEG1) ? 0 : (m0 < SEG2) ? 1 : (m0 < SEG3) ? 2 : 3;
    const float* Abase = (seg == 0 || seg == 2) ? vf : (seg == 1 ? tf : af);
    const float* bias = (seg == 0) ? bv : (seg == 1) ? bt : (seg == 2) ? bp : ba;
    const __nv_bfloat16* wth = g_wt_hi[seg];
    const __nv_bfloat16* wtl = g_wt_lo[seg];

    float* dstbase;
    int mrel;
    if (seg == 0)      { dstbase = out;            mrel = m0; }
    else if (seg == 1) { dstbase = out + Bb * EE;  mrel = m0 - SEG1; }
    else if (seg == 2) { dstbase = g_pat;          mrel = m0 - SEG2; }
    else               { dstbase = g_att;          mrel = m0 - SEG3; }

    // row source offsets (floats)
    if (t < 128) {
        const int m = m0 + t;
        int off;
        if (m < SEG1)        off = m * (193 * 768);
        else if (m < SEG2)   off = (m - SEG1) * 768;
        else if (m < SEG3) { const int mm = m - SEG2;
                             off = ((mm / 192) * 193 + 1 + (mm % 192)) * 768; }
        else                 off = (m - SEG3) * 768;
        sRowOff[t] = off;
    }
    __syncthreads();

    const uint32_t smem_u = smem_u32(dynsm);
    const int warp_m = warp & 1;          // 2 m-warps (64 rows each)
    const int warp_n = warp >> 1;         // 4 n-warps (32 cols each)
    const int g = lane >> 3, lr = lane & 7;
    const uint32_t aoff = (uint32_t)((warp_m * 64 + (g & 1) * 8 + lr) * ROWB + (g >> 1) * 16);
    const uint32_t boff = (uint32_t)((warp_n * 32 + (g & 1) * 8 + lr) * ROWB + (g >> 1) * 16);

    // A-loader mapping: 4 passes, each thread one float4
    const int arow = t >> 3;              // + 32*pass
    const int acol = (t & 7) * 4;         // floats
    // B-loader mapping: 2 passes of 256 cp16 per operand
    const int brow0 = t >> 2;             // + 64*pass
    const int bseg = (t & 3) * 16;        // bytes within 64B row

    float acc[4][4][4] = {};
    float4 aReg[4];

    // ---- prologue: stage 0 ----
#pragma unroll
    for (int p = 0; p < 4; p++)
        aReg[p] = *(const float4*)(Abase + sRowOff[p * 32 + arow] + acol);
#pragma unroll
    for (int q = 0; q < 2; q++) {
        const int row = brow0 + q * 64;
        const size_t gb = (size_t)(bn * 128 + row) * 1536 + bseg;
        const uint32_t sb = smem_u + (uint32_t)(row * ROWB + bseg);
        cp16(sb + OFF_BH, (const char*)wth + gb);
        cp16(sb + OFF_BL, (const char*)wtl + gb);
    }
    CP_COMMIT();
    {
        char* st = dynsm;
#pragma unroll
        for (int p = 0; p < 4; p++) {
            const float4 v = aReg[p];
            const __nv_bfloat16 h0 = __float2bfloat16(v.x), h1 = __float2bfloat16(v.y);
            const __nv_bfloat16 h2 = __float2bfloat16(v.z), h3 = __float2bfloat16(v.w);
            const __nv_bfloat16 l0 = __float2bfloat16(v.x - __bfloat162float(h0));
            const __nv_bfloat16 l1 = __float2bfloat16(v.y - __bfloat162float(h1));
            const __nv_bfloat16 l2 = __float2bfloat16(v.z - __bfloat162float(h2));
            const __nv_bfloat16 l3 = __float2bfloat16(v.w - __bfloat162float(h3));
            __nv_bfloat162 hp0 = __halves2bfloat162(h0, h1), hp1 = __halves2bfloat162(h2, h3);
            __nv_bfloat162 lp0 = __halves2bfloat162(l0, l1), lp1 = __halves2bfloat162(l2, l3);
            uint2 hv, lv;
            hv.x = *(uint32_t*)&hp0; hv.y = *(uint32_t*)&hp1;
            lv.x = *(uint32_t*)&lp0; lv.y = *(uint32_t*)&lp1;
            const int byo = (p * 32 + arow) * ROWB + (t & 7) * 8;
            *(uint2*)(st + OFF_AH + byo) = hv;
            *(uint2*)(st + OFF_AL + byo) = lv;
        }
    }
    CP_WAIT0();
    __syncthreads();

    // ---- main loop ----
    for (int c = 0; c < NCH; c++) {
        const int cur = c & 1;
        const int nxt = cur ^ 1;
        if (c + 1 < NCH) {
            const int kc = (c + 1) * BKC;
#pragma unroll
            for (int p = 0; p < 4; p++)
                aReg[p] = *(const float4*)(Abase + sRowOff[p * 32 + arow] + kc + acol);
            const uint32_t stb = smem_u + nxt * STAGESZ;
#pragma unroll
            for (int q = 0; q < 2; q++) {
                const int row = brow0 + q * 64;
                const size_t gb = (size_t)(bn * 128 + row) * 1536 + kc * 2 + bseg;
                const uint32_t sb = stb + (uint32_t)(row * ROWB + bseg);
                cp16(sb + OFF_BH, (const char*)wth + gb);
                cp16(sb + OFF_BL, (const char*)wtl + gb);
            }
            CP_COMMIT();
        }

        // compute on cur
        const uint32_t sb = smem_u + cur * STAGESZ;
#pragma unroll
        for (int ks = 0; ks < 2; ks++) {
            uint32_t ah[4][4], al[4][4], bh[2][4], bl[2][4];
#pragma unroll
            for (int mt = 0; mt < 4; mt++) {
                LDSM4(ah[mt], sb + OFF_AH + aoff + mt * (16 * ROWB) + ks * 32);
                LDSM4(al[mt], sb + OFF_AL + aoff + mt * (16 * ROWB) + ks * 32);
            }
#pragma unroll
            for (int n2 = 0; n2 < 2; n2++) {
                LDSM4(bh[n2], sb + OFF_BH + boff + n2 * (16 * ROWB) + ks * 32);
                LDSM4(bl[n2], sb + OFF_BL + boff + n2 * (16 * ROWB) + ks * 32);
            }
#pragma unroll
            for (int mt = 0; mt < 4; mt++)
#pragma unroll
                for (int nt = 0; nt < 4; nt++) {
                    float* cc = acc[mt][nt];
                    const int n2 = nt >> 1, no = nt & 1;
                    MMA(cc, ah[mt], bh[n2][no], bh[n2][2 + no]);
                    MMA(cc, ah[mt], bl[n2][no], bl[n2][2 + no]);
                    MMA(cc, al[mt], bh[n2][no], bh[n2][2 + no]);
                }
        }

        if (c + 1 < NCH) {
            char* st = dynsm + nxt * STAGESZ;
#pragma unroll
            for (int p = 0; p < 4; p++) {
                const float4 v = aReg[p];
                const __nv_bfloat16 h0 = __float2bfloat16(v.x), h1 = __float2bfloat16(v.y);
                const __nv_bfloat16 h2 = __float2bfloat16(v.z), h3 = __float2bfloat16(v.w);
                const __nv_bfloat16 l0 = __float2bfloat16(v.x - __bfloat162float(h0));
                const __nv_bfloat16 l1 = __float2bfloat16(v.y - __bfloat162float(h1));
                const __nv_bfloat16 l2 = __float2bfloat16(v.z - __bfloat162float(h2));
                const __nv_bfloat16 l3 = __float2bfloat16(v.w - __bfloat162float(h3));
                __nv_bfloat162 hp0 = __halves2bfloat162(h0, h1), hp1 = __halves2bfloat162(h2, h3);
                __nv_bfloat162 lp0 = __halves2bfloat162(l0, l1), lp1 = __halves2bfloat162(l2, l3);
                uint2 hv, lv;
                hv.x = *(uint32_t*)&hp0; hv.y = *(uint32_t*)&hp1;
                lv.x = *(uint32_t*)&lp0; lv.y = *(uint32_t*)&lp1;
                const int byo = (p * 32 + arow) * ROWB + (t & 7) * 8;
                *(uint2*)(st + OFF_AH + byo) = hv;
                *(uint2*)(st + OFF_AL + byo) = lv;
            }
            CP_WAIT0();
        }
        __syncthreads();
    }

    // ---- epilogue: bias add + store ----
    const int r0 = lane >> 2;
    const int cp2 = (lane & 3) * 2;
#pragma unroll
    for (int nt = 0; nt < 4; nt++) {
        const int gcol = bn * 128 + warp_n * 32 + nt * 8 + cp2;
        const float2 bb = *(const float2*)(bias + gcol);
#pragma unroll
        for (int mt = 0; mt < 4; mt++) {
            const int row0 = mrel + warp_m * 64 + mt * 16 + r0;
            float2 v0, v1;
            v0.x = acc[mt][nt][0] + bb.x; v0.y = acc[mt][nt][1] + bb.y;
            v1.x = acc[mt][nt][2] + bb.x; v1.y = acc[mt][nt][3] + bb.y;
            *(float2*)(dstbase + (size_t)row0 * EE + gcol) = v0;
            *(float2*)(dstbase + (size_t)(row0 + 8) * EE + gcol) = v1;
        }
    }
}

// ---------------- sim with fused L2 normalization ----------------
__global__ __launch_bounds__(256)
void sim_kernel(const float* __restrict__ pat, const float* __restrict__ att,
                float* __restrict__ sim)
{
    const int b = blockIdx.x;
    __shared__ float s_att[AA * EE];
    const int t = threadIdx.x;
    const int warp = t >> 5, lane = t & 31;

    // warp w normalizes att row w
    {
        const float* ar = att + ((size_t)b * AA + warp) * EE;
        float v[8];
        float ss = 0.f;
#pragma unroll
        for (int i = 0; i < 8; i++) { v[i] = ar[lane + 32 * i]; ss += v[i] * v[i]; }
#pragma unroll
        for (int o = 16; o; o >>= 1) ss += __shfl_xor_sync(0xffffffffu, ss, o);
        const float inv = 1.f / fmaxf(sqrtf(ss), 1e-12f);
#pragma unroll
        for (int i = 0; i < 8; i++) s_att[warp * EE + lane + 32 * i] = v[i] * inv;
    }
    __syncthreads();

    for (int p = warp; p < Pp; p += 8) {
        const float* pr = pat + ((size_t)b * Pp + p) * EE;
        float acc[AA] = {};
        float ss = 0.f;
        for (int e = lane; e < EE; e += 32) {
            const float v = pr[e];
            ss += v * v;
#pragma unroll
            for (int a = 0; a < AA; a++) acc[a] += v * s_att[a * EE + e];
        }
#pragma unroll
        for (int o = 16; o; o >>= 1) ss += __shfl_xor_sync(0xffffffffu, ss, o);
#pragma unroll
        for (int a = 0; a < AA; a++)
#pragma unroll
            for (int o = 16; o; o >>= 1) acc[a] += __shfl_xor_sync(0xffffffffu, acc[a], o);
        const float inv = 1.f / fmaxf(sqrtf(ss), 1e-12f);
        if (lane == 0) {
#pragma unroll
            for (int a = 0; a < AA; a++)
                sim[(size_t)b * AA * Pp + a * Pp + p] = acc[a] * inv;
        }
    }
}

// ---------------- K-round masked Hungarian (JV), one warp per batch ------
__global__ __launch_bounds__(32)
void hungarian_kernel(const float* __restrict__ simg, float* __restrict__ out)
{
    const int b = blockIdx.x;
    const int lane = threadIdx.x;
    const int M = Pp;
    const float FINF = 1e30f;

    __shared__ float cost[AA][Pp];
    __shared__ float vsh[Pp + 1];
    __shared__ float minv[Pp + 1];
    __shared__ float ush[AA + 1];
    __shared__ int   psh[Pp + 1];
    __shared__ int   waysh[Pp + 1];
    __shared__ int   usedsh[Pp + 1];

    for (int idx = lane; idx < AA * Pp; idx += 32)
        cost[idx / Pp][idx % Pp] = -simg[(size_t)b * AA * Pp + idx];
    __syncwarp();

    float total = 0.f;

    for (int round = 0; round < KK; round++) {
        for (int j = lane; j <= M; j += 32) { vsh[j] = 0.f; psh[j] = 0; }
        if (lane < AA + 1) ush[lane] = 0.f;
        __syncwarp();

        for (int i = 1; i <= AA; i++) {
            if (lane == 0) psh[0] = i;
            for (int j = lane; j <= M; j += 32) { minv[j] = FINF; usedsh[j] = 0; }
            __syncwarp();
            int j0 = 0;
            while (true) {
                if (lane == 0) usedsh[j0] = 1;
                __syncwarp();
                const int i0 = psh[j0];
                const float ui0 = ush[i0];

                float best = FINF;
                int bestj = 1 << 20;
                for (int j = lane + 1; j <= M; j += 32) {
                    if (!usedsh[j]) {
                        float cur = cost[i0 - 1][j - 1] - ui0 - vsh[j];
                        if (cur < minv[j]) { minv[j] = cur; waysh[j] = j0; }
                        const float mv = minv[j];
                        if (mv < best || (mv == best && j < bestj)) { best = mv; bestj = j; }
                    }
                }
                __syncwarp();
#pragma unroll
                for (int o = 16; o; o >>= 1) {
                    float ob = __shfl_xor_sync(0xffffffffu, best, o);
                    int   oj = __shfl_xor_sync(0xffffffffu, bestj, o);
                    if (ob < best || (ob == best && oj < bestj)) { best = ob; bestj = oj; }
                }
                const float delta = best;
                const int j1 = bestj;

                for (int j = lane; j <= M; j += 32) {
                    if (usedsh[j]) { ush[psh[j]] += delta; vsh[j] -= delta; }
                    else           { minv[j] -= delta; }
                }
                __syncwarp();
                j0 = j1;
                if (psh[j0] == 0) break;
            }
            if (lane == 0) {
                int jc = j0;
                while (jc) { int jn = waysh[jc]; psh[jc] = psh[jn]; jc = jn; }
            }
            __syncwarp();
        }

        for (int j = lane + 1; j <= M; j += 32) {
            const int r = psh[j];
            if (r) {
                total += -cost[r - 1][j - 1];
                cost[r - 1][j - 1] = 100.f;
            }
        }
        __syncwarp();
    }

#pragma unroll
    for (int o = 16; o; o >>= 1) total += __shfl_xor_sync(0xffffffffu, total, o);
    if (lane == 0) out[b] = total * (1.f / (KK * AA));
}

// ---------------- launch ----------------
extern "C" void kernel_launch(void* const* d_in, const int* in_sizes, int n_in,
                              void* d_out, int out_size)
{
    const float* vf = (const float*)d_in[0];
    const float* tf = (const float*)d_in[1];
    const float* af = (const float*)d_in[2];
    const float* Wv = (const float*)d_in[4];
    const float* bv = (const float*)d_in[5];
    const float* Wt = (const float*)d_in[6];
    const float* bt = (const float*)d_in[7];
    const float* Wp = (const float*)d_in[8];
    const float* bp = (const float*)d_in[9];
    const float* Wa = (const float*)d_in[10];
    const float* ba = (const float*)d_in[11];

    float* out = (float*)d_out;
    float* ls = out + 2 * Bb * EE;

    float *gpat, *gatt, *gsim;
    cudaGetSymbolAddress((void**)&gpat, g_pat);
    cudaGetSymbolAddress((void**)&gatt, g_att);
    cudaGetSymbolAddress((void**)&gsim, g_sim);

    cudaFuncSetAttribute(gemm_mma, cudaFuncAttributeMaxDynamicSharedMemorySize, DYNSZ);

    wsplit_kernel<<<dim3(24, 8, 4), dim3(32, 8)>>>(Wv, Wt, Wp, Wa);
    gemm_mma<<<dim3(MTILES, 2), 256, DYNSZ>>>(vf, tf, af, bv, bt, bp, ba, out);
    sim_kernel<<<Bb, 256>>>(gpat, gatt, gsim);
    hungarian_kernel<<<Bb, 32>>>(gsim, ls);
}

// round 4
// speedup vs baseline: 2.5216x; 1.0953x over previous
#include <cuda_runtime.h>
#include <cuda_bf16.h>
#include <cstdint>

// ---------------- constants ----------------
#define Bb   256
#define Pp   192
#define DD   768
#define EE   256
#define AA   8
#define KK   4

#define M_TOTAL   51712          // 256(ve) + 256(te) + 49152(pat) + 2048(att)
#define SEG1      256
#define SEG2      512
#define SEG3      49664
#define MTILES    404            // M_TOTAL / 128
#define BKC       64             // K per chunk (bf16 elems)
#define NCH       12             // 768 / 64

// SMEM: 4 operands (AH, AL, BH, BL), each 128 rows x 144 bytes, double buffered
#define ROWB    144
#define OPSZ    (128 * ROWB)     // 18432
#define OFF_AH  0
#define OFF_AL  (OPSZ)
#define OFF_BH  (2 * OPSZ)
#define OFF_BL  (3 * OPSZ)
#define STAGESZ (4 * OPSZ)       // 73728
#define DYNSZ   (2 * STAGESZ)    // 147456

// ---------------- scratch ----------------
__device__ float g_pat[(size_t)Bb * Pp * EE];   // unnormalized patch embed
__device__ float g_att[(size_t)Bb * AA * EE];   // unnormalized att embed
__device__ float g_sim[(size_t)Bb * AA * Pp];
__device__ __nv_bfloat16 g_wt_hi[4][256 * 768]; // W^T hi bf16, [N][K]
__device__ __nv_bfloat16 g_wt_lo[4][256 * 768]; // W^T lo bf16

// ---------------- PTX helpers ----------------
static __device__ __forceinline__ uint32_t smem_u32(const void* p) {
    uint32_t a;
    asm("{ .reg .u64 t; cvta.to.shared.u64 t, %1; cvt.u32.u64 %0, t; }"
        : "=r"(a) : "l"(p));
    return a;
}

#define LDSM4(r, addr) \
    asm volatile("ldmatrix.sync.aligned.m8n8.x4.shared.b16 {%0,%1,%2,%3}, [%4];" \
        : "=r"((r)[0]), "=r"((r)[1]), "=r"((r)[2]), "=r"((r)[3]) : "r"(addr))

#define MMA(c, a, b0, b1) \
    asm volatile("mma.sync.aligned.m16n8k16.row.col.f32.bf16.bf16.f32 " \
        "{%0,%1,%2,%3}, {%4,%5,%6,%7}, {%8,%9}, {%0,%1,%2,%3};" \
        : "+f"((c)[0]), "+f"((c)[1]), "+f"((c)[2]), "+f"((c)[3]) \
        : "r"((a)[0]), "r"((a)[1]), "r"((a)[2]), "r"((a)[3]), "r"(b0), "r"(b1))

static __device__ __forceinline__ void cp16(uint32_t s, const void* g) {
    asm volatile("cp.async.cg.shared.global [%0], [%1], 16;" :: "r"(s), "l"(g));
}
#define CP_COMMIT() asm volatile("cp.async.commit_group;" ::: "memory")
#define CP_WAIT0()  asm volatile("cp.async.wait_group 0;" ::: "memory")

// ---------------- W transpose + bf16 hi/lo split ----------------
__global__ void wsplit_kernel(const float* __restrict__ W0, const float* __restrict__ W1,
                              const float* __restrict__ W2, const float* __restrict__ W3)
{
    const int z = blockIdx.z;
    const float* W = (z == 0) ? W0 : (z == 1) ? W1 : (z == 2) ? W2 : W3;
    __shared__ float tile[32][33];
    const int tx = threadIdx.x, ty = threadIdx.y;
    const int k0 = blockIdx.x * 32, n0 = blockIdx.y * 32;
#pragma unroll
    for (int i = 0; i < 4; i++)
        tile[ty + 8 * i][tx] = W[(size_t)(k0 + ty + 8 * i) * 256 + n0 + tx];
    __syncthreads();
#pragma unroll
    for (int i = 0; i < 4; i++) {
        const float v = tile[tx][ty + 8 * i];
        const __nv_bfloat16 hi = __float2bfloat16(v);
        const __nv_bfloat16 lo = __float2bfloat16(v - __bfloat162float(hi));
        const size_t o = (size_t)(n0 + ty + 8 * i) * 768 + k0 + tx;
        g_wt_hi[z][o] = hi;
        g_wt_lo[z][o] = lo;
    }
}

// ---------------- A convert+store helper ----------------
static __device__ __forceinline__ void store_a(char* st, const float4* aReg,
                                               int arow, int t)
{
#pragma unroll
    for (int p = 0; p < 8; p++) {
        const float4 v = aReg[p];
        const __nv_bfloat16 h0 = __float2bfloat16(v.x), h1 = __float2bfloat16(v.y);
        const __nv_bfloat16 h2 = __float2bfloat16(v.z), h3 = __float2bfloat16(v.w);
        const __nv_bfloat16 l0 = __float2bfloat16(v.x - __bfloat162float(h0));
        const __nv_bfloat16 l1 = __float2bfloat16(v.y - __bfloat162float(h1));
        const __nv_bfloat16 l2 = __float2bfloat16(v.z - __bfloat162float(h2));
        const __nv_bfloat16 l3 = __float2bfloat16(v.w - __bfloat162float(h3));
        __nv_bfloat162 hp0 = __halves2bfloat162(h0, h1), hp1 = __halves2bfloat162(h2, h3);
        __nv_bfloat162 lp0 = __halves2bfloat162(l0, l1), lp1 = __halves2bfloat162(l2, l3);
        uint2 hv, lv;
        hv.x = *(uint32_t*)&hp0; hv.y = *(uint32_t*)&hp1;
        lv.x = *(uint32_t*)&lp0; lv.y = *(uint32_t*)&lp1;
        const int byo = (p * 16 + arow) * ROWB + (t & 15) * 8;
        *(uint2*)(st + OFF_AH + byo) = hv;
        *(uint2*)(st + OFF_AL + byo) = lv;
    }
}

// ---------------- fused HMMA GEMM: C[m,256] = A[m,768] @ W + bias ----------
__global__ __launch_bounds__(256, 1)
void gemm_mma(const float* __restrict__ vf, const float* __restrict__ tf,
              const float* __restrict__ af,
              const float* __restrict__ bv, const float* __restrict__ bt,
              const float* __restrict__ bp, const float* __restrict__ ba,
              float* __restrict__ out)
{
    extern __shared__ char dynsm[];
    __shared__ int sRowOff[128];

    const int t = threadIdx.x;
    const int warp = t >> 5;
    const int lane = t & 31;
    const int m0 = blockIdx.x * 128;
    const int bn = blockIdx.y;           // 0 or 1 (N halves)

    const int seg = (m0 < SEG1) ? 0 : (m0 < SEG2) ? 1 : (m0 < SEG3) ? 2 : 3;
    const float* Abase = (seg == 0 || seg == 2) ? vf : (seg == 1 ? tf : af);
    const float* bias = (seg == 0) ? bv : (seg == 1) ? bt : (seg == 2) ? bp : ba;
    const __nv_bfloat16* wth = g_wt_hi[seg];
    const __nv_bfloat16* wtl = g_wt_lo[seg];

    float* dstbase;
    int mrel;
    if (seg == 0)      { dstbase = out;            mrel = m0; }
    else if (seg == 1) { dstbase = out + Bb * EE;  mrel = m0 - SEG1; }
    else if (seg == 2) { dstbase = g_pat;          mrel = m0 - SEG2; }
    else               { dstbase = g_att;          mrel = m0 - SEG3; }

    // row source offsets (floats)
    if (t < 128) {
        const int m = m0 + t;
        int off;
        if (m < SEG1)        off = m * (193 * 768);
        else if (m < SEG2)   off = (m - SEG1) * 768;
        else if (m < SEG3) { const int mm = m - SEG2;
                             off = ((mm / 192) * 193 + 1 + (mm % 192)) * 768; }
        else                 off = (m - SEG3) * 768;
        sRowOff[t] = off;
    }
    __syncthreads();

    const uint32_t smem_u = smem_u32(dynsm);
    const int warp_m = warp & 1;          // 2 m-warps (64 rows each)
    const int warp_n = warp >> 1;         // 4 n-warps (32 cols each)
    const int g = lane >> 3, lr = lane & 7;
    const uint32_t aoff = (uint32_t)((warp_m * 64 + (g & 1) * 8 + lr) * ROWB + (g >> 1) * 16);
    const uint32_t boff = (uint32_t)((warp_n * 32 + (g & 1) * 8 + lr) * ROWB + (g >> 1) * 16);

    // A-loader mapping: 8 passes, each thread one float4 (128 rows x 64 floats)
    const int arow = t >> 4;              // 0..15, + 16*pass
    const int acol = (t & 15) * 4;        // floats
    // B-loader mapping: 4 passes of cp16 per operand (128 rows x 128 bytes)
    const int brow = t >> 3;              // 0..31, + 32*pass
    const int bseg = (t & 7) * 16;        // bytes within 128B row

    float acc[4][4][4] = {};
    float4 aReg[8];

    // ---- prologue: stage 0 ----
#pragma unroll
    for (int p = 0; p < 8; p++)
        aReg[p] = *(const float4*)(Abase + sRowOff[p * 16 + arow] + acol);
#pragma unroll
    for (int q = 0; q < 4; q++) {
        const int row = brow + q * 32;
        const size_t gb = (size_t)(bn * 128 + row) * 1536 + bseg;
        const uint32_t sb = smem_u + (uint32_t)(row * ROWB + bseg);
        cp16(sb + OFF_BH, (const char*)wth + gb);
        cp16(sb + OFF_BL, (const char*)wtl + gb);
    }
    CP_COMMIT();
    store_a(dynsm, aReg, arow, t);
    CP_WAIT0();
    __syncthreads();

    // ---- main loop ----
    for (int c = 0; c < NCH; c++) {
        const int cur = c & 1;
        const int nxt = cur ^ 1;
        if (c + 1 < NCH) {
            const int kc = (c + 1) * BKC;
#pragma unroll
            for (int p = 0; p < 8; p++)
                aReg[p] = *(const float4*)(Abase + sRowOff[p * 16 + arow] + kc + acol);
            const uint32_t stb = smem_u + nxt * STAGESZ;
#pragma unroll
            for (int q = 0; q < 4; q++) {
                const int row = brow + q * 32;
                const size_t gb = (size_t)(bn * 128 + row) * 1536 + kc * 2 + bseg;
                const uint32_t sb = stb + (uint32_t)(row * ROWB + bseg);
                cp16(sb + OFF_BH, (const char*)wth + gb);
                cp16(sb + OFF_BL, (const char*)wtl + gb);
            }
            CP_COMMIT();
        }

        // compute on cur
        const uint32_t sb = smem_u + cur * STAGESZ;
#pragma unroll
        for (int ks = 0; ks < 4; ks++) {
            uint32_t ah[4][4], al[4][4], bh[2][4], bl[2][4];
#pragma unroll
            for (int mt = 0; mt < 4; mt++) {
                LDSM4(ah[mt], sb + OFF_AH + aoff + mt * (16 * ROWB) + ks * 32);
                LDSM4(al[mt], sb + OFF_AL + aoff + mt * (16 * ROWB) + ks * 32);
            }
#pragma unroll
            for (int n2 = 0; n2 < 2; n2++) {
                LDSM4(bh[n2], sb + OFF_BH + boff + n2 * (16 * ROWB) + ks * 32);
                LDSM4(bl[n2], sb + OFF_BL + boff + n2 * (16 * ROWB) + ks * 32);
            }
#pragma unroll
            for (int mt = 0; mt < 4; mt++)
#pragma unroll
                for (int nt = 0; nt < 4; nt++) {
                    float* cc = acc[mt][nt];
                    const int n2 = nt >> 1, no = nt & 1;
                    MMA(cc, ah[mt], bh[n2][no], bh[n2][2 + no]);
                    MMA(cc, ah[mt], bl[n2][no], bl[n2][2 + no]);
                    MMA(cc, al[mt], bh[n2][no], bh[n2][2 + no]);
                }
        }

        if (c + 1 < NCH) {
            store_a(dynsm + nxt * STAGESZ, aReg, arow, t);
            CP_WAIT0();
        }
        __syncthreads();
    }

    // ---- epilogue: bias add + store ----
    const int r0 = lane >> 2;
    const int cp2 = (lane & 3) * 2;
#pragma unroll
    for (int nt = 0; nt < 4; nt++) {
        const int gcol = bn * 128 + warp_n * 32 + nt * 8 + cp2;
        const float2 bb = *(const float2*)(bias + gcol);
#pragma unroll
        for (int mt = 0; mt < 4; mt++) {
            const int row0 = mrel + warp_m * 64 + mt * 16 + r0;
            float2 v0, v1;
            v0.x = acc[mt][nt][0] + bb.x; v0.y = acc[mt][nt][1] + bb.y;
            v1.x = acc[mt][nt][2] + bb.x; v1.y = acc[mt][nt][3] + bb.y;
            *(float2*)(dstbase + (size_t)row0 * EE + gcol) = v0;
            *(float2*)(dstbase + (size_t)(row0 + 8) * EE + gcol) = v1;
        }
    }
}

// ---------------- sim v2: full pat tile in SMEM, fused normalization -------
#define PATPITCH 257
__global__ __launch_bounds__(256)
void sim_kernel(const float* __restrict__ pat, const float* __restrict__ att,
                float* __restrict__ sim)
{
    extern __shared__ float pat_s[];              // [192][257]
    __shared__ float inv_s[Pp];
    const int b = blockIdx.x;
    const int t = threadIdx.x;
    const int warp = t >> 5, lane = t & 31;

    // load pat[b] -> shared (each iteration = one full row, coalesced)
    const float* pb = pat + (size_t)b * Pp * EE;
#pragma unroll
    for (int i = 0; i < Pp; i += 1) {
        // t covers one row (256 floats) per step i
        pat_s[i * PATPITCH + t] = pb[i * EE + t];
    }

    // att row 'warp' -> registers, normalized
    float a[8];
    {
        const float* ar = att + ((size_t)b * AA + warp) * EE;
        float ss = 0.f;
#pragma unroll
        for (int i = 0; i < 8; i++) { a[i] = ar[lane + 32 * i]; ss += a[i] * a[i]; }
#pragma unroll
        for (int o = 16; o; o >>= 1) ss += __shfl_xor_sync(0xffffffffu, ss, o);
        const float inv = 1.f / fmaxf(sqrtf(ss), 1e-12f);
#pragma unroll
        for (int i = 0; i < 8; i++) a[i] *= inv;
    }
    __syncthreads();

    // pat row inverse norms
    if (t < Pp) {
        const float* pr = pat_s + t * PATPITCH;
        float ss = 0.f;
#pragma unroll 8
        for (int e = 0; e < EE; e++) ss += pr[e] * pr[e];
        inv_s[t] = 1.f / fmaxf(sqrtf(ss), 1e-12f);
    }
    __syncthreads();

    // warp w computes sim[b][w][p] for all p
    float* srow = sim + ((size_t)b * AA + warp) * Pp;
    for (int p = 0; p < Pp; p++) {
        const float* pr = pat_s + p * PATPITCH + lane;
        float acc = 0.f;
#pragma unroll
        for (int i = 0; i < 8; i++) acc += a[i] * pr[32 * i];
#pragma unroll
        for (int o = 16; o; o >>= 1) acc += __shfl_xor_sync(0xffffffffu, acc, o);
        if (lane == 0) srow[p] = acc * inv_s[p];
    }
}

// ---------------- Hungarian v2: register-resident JV, 4 batches/block ------
#define HW 4
__global__ __launch_bounds__(32 * HW)
void hungarian_kernel(const float* __restrict__ simg, float* __restrict__ out)
{
    __shared__ float cost_s[HW][AA][Pp];
    __shared__ float u_s[HW][AA + 1];
    __shared__ int   p_s[HW][Pp + 1];
    __shared__ short way_s[HW][Pp + 1];

    const int w = threadIdx.x >> 5;
    const int lane = threadIdx.x & 31;
    const int b = blockIdx.x * HW + w;
    const float FINF = 1e30f;

    float (*cost)[Pp] = cost_s[w];
    float* u = u_s[w];
    int*   p = p_s[w];
    short* way = way_s[w];

    for (int idx = lane; idx < AA * Pp; idx += 32)
        cost[idx / Pp][idx % Pp] = -simg[(size_t)b * AA * Pp + idx];

    float total = 0.f;

    for (int round = 0; round < KK; round++) {
        float v[6];
#pragma unroll
        for (int s = 0; s < 6; s++) v[s] = 0.f;
        for (int j = lane; j <= Pp; j += 32) p[j] = 0;
        if (lane < AA + 1) u[lane] = 0.f;
        __syncwarp();

        for (int i = 1; i <= AA; i++) {
            if (lane == 0) p[0] = i;
            float minv[6];
            unsigned usedm = 0;
#pragma unroll
            for (int s = 0; s < 6; s++) minv[s] = FINF;
            __syncwarp();

            int j0 = 0;
            bool used0 = false;
            while (true) {
                if (j0 == 0) used0 = true;
                else {
                    const int cidx = j0 - 1;
                    if ((cidx & 31) == lane) usedm |= 1u << (cidx >> 5);
                }
                const int i0 = p[j0];
                const float ui0 = u[i0];
                const float* crow = cost[i0 - 1];

                float best = FINF;
                int bestj = 1 << 20;
#pragma unroll
                for (int s = 0; s < 6; s++) {
                    if (!((usedm >> s) & 1)) {
                        const int c = s * 32 + lane;
                        const float cur = crow[c] - ui0 - v[s];
                        if (cur < minv[s]) { minv[s] = cur; way[c + 1] = (short)j0; }
                        const float mv = minv[s];
                        const int j = c + 1;
                        if (mv < best || (mv == best && j < bestj)) { best = mv; bestj = j; }
                    }
                }
#pragma unroll
                for (int o = 16; o; o >>= 1) {
                    const float ob = __shfl_xor_sync(0xffffffffu, best, o);
                    const int   oj = __shfl_xor_sync(0xffffffffu, bestj, o);
                    if (ob < best || (ob == best && oj < bestj)) { best = ob; bestj = oj; }
                }
                const float delta = best;
                const int j1 = bestj;

                if (used0 && lane == 0) u[p[0]] += delta;
#pragma unroll
                for (int s = 0; s < 6; s++) {
                    if ((usedm >> s) & 1) {
                        const int j = s * 32 + lane + 1;
                        v[s] -= delta;
                        u[p[j]] += delta;
                    } else {
                        minv[s] -= delta;
                    }
                }
                __syncwarp();
                j0 = j1;
                if (p[j0] == 0) break;
            }
            __syncwarp();
            if (lane == 0) {
                int jc = j0;
                while (jc) { const int jn = way[jc]; p[jc] = p[jn]; jc = jn; }
            }
            __syncwarp();
        }

        // collect matched values + mask
#pragma unroll
        for (int s = 0; s < 6; s++) {
            const int c = s * 32 + lane;
            const int r = p[c + 1];
            if (r) {
                total += -cost[r - 1][c];
                cost[r - 1][c] = 100.f;
            }
        }
        __syncwarp();
    }

#pragma unroll
    for (int o = 16; o; o >>= 1) total += __shfl_xor_sync(0xffffffffu, total, o);
    if (lane == 0) out[b] = total * (1.f / (KK * AA));
}

// ---------------- launch ----------------
extern "C" void kernel_launch(void* const* d_in, const int* in_sizes, int n_in,
                              void* d_out, int out_size)
{
    const float* vf = (const float*)d_in[0];
    const float* tf = (const float*)d_in[1];
    const float* af = (const float*)d_in[2];
    const float* Wv = (const float*)d_in[4];
    const float* bv = (const float*)d_in[5];
    const float* Wt = (const float*)d_in[6];
    const float* bt = (const float*)d_in[7];
    const float* Wp = (const float*)d_in[8];
    const float* bp = (const float*)d_in[9];
    const float* Wa = (const float*)d_in[10];
    const float* ba = (const float*)d_in[11];

    float* out = (float*)d_out;
    float* ls = out + 2 * Bb * EE;

    float *gpat, *gatt, *gsim;
    cudaGetSymbolAddress((void**)&gpat, g_pat);
    cudaGetSymbolAddress((void**)&gatt, g_att);
    cudaGetSymbolAddress((void**)&gsim, g_sim);

    cudaFuncSetAttribute(gemm_mma, cudaFuncAttributeMaxDynamicSharedMemorySize, DYNSZ);
    cudaFuncSetAttribute(sim_kernel, cudaFuncAttributeMaxDynamicSharedMemorySize,
                         Pp * PATPITCH * 4);

    wsplit_kernel<<<dim3(24, 8, 4), dim3(32, 8)>>>(Wv, Wt, Wp, Wa);
    gemm_mma<<<dim3(MTILES, 2), 256, DYNSZ>>>(vf, tf, af, bv, bt, bp, ba, out);
    sim_kernel<<<Bb, 256, Pp * PATPITCH * 4>>>(gpat, gatt, gsim);
    hungarian_kernel<<<Bb / HW, 32 * HW>>>(gsim, ls);
}

// round 5
// speedup vs baseline: 3.2691x; 1.2964x over previous
#include <cuda_runtime.h>
#include <cuda_bf16.h>
#include <cuda_fp16.h>
#include <cstdint>

// ---------------- constants ----------------
#define Bb   256
#define Pp   192
#define DD   768
#define EE   256
#define AA   8
#define KK   4

#define M_TOTAL   51712          // 256(ve) + 256(te) + 49152(pat) + 2048(att)
#define SEG1      256
#define SEG2      512
#define SEG3      49664
#define MTILES    404            // M_TOTAL / 128
#define BKC       64             // K per chunk (fp16 elems)
#define NCH       12             // 768 / 64

// SMEM: 3 operands (AH, AL, B), each 128 rows x 144 bytes, double buffered
#define ROWB    144
#define OPSZ    (128 * ROWB)     // 18432
#define OFF_AH  0
#define OFF_AL  (OPSZ)
#define OFF_B   (2 * OPSZ)
#define STAGESZ (3 * OPSZ)       // 55296
#define DYNSZ   (2 * STAGESZ)    // 110592

// ---------------- scratch ----------------
__device__ float g_pat[(size_t)Bb * Pp * EE];   // unnormalized patch embed
__device__ float g_att[(size_t)Bb * AA * EE];   // unnormalized att embed
__device__ float g_sim[(size_t)Bb * AA * Pp];
__device__ __half g_wt[4][256 * 768];           // W^T fp16, [N][K]

// ---------------- PTX helpers ----------------
static __device__ __forceinline__ uint32_t smem_u32(const void* p) {
    uint32_t a;
    asm("{ .reg .u64 t; cvta.to.shared.u64 t, %1; cvt.u32.u64 %0, t; }"
        : "=r"(a) : "l"(p));
    return a;
}

#define LDSM4(r, addr) \
    asm volatile("ldmatrix.sync.aligned.m8n8.x4.shared.b16 {%0,%1,%2,%3}, [%4];" \
        : "=r"((r)[0]), "=r"((r)[1]), "=r"((r)[2]), "=r"((r)[3]) : "r"(addr))

#define MMA(c, a, b0, b1) \
    asm volatile("mma.sync.aligned.m16n8k16.row.col.f32.f16.f16.f32 " \
        "{%0,%1,%2,%3}, {%4,%5,%6,%7}, {%8,%9}, {%0,%1,%2,%3};" \
        : "+f"((c)[0]), "+f"((c)[1]), "+f"((c)[2]), "+f"((c)[3]) \
        : "r"((a)[0]), "r"((a)[1]), "r"((a)[2]), "r"((a)[3]), "r"(b0), "r"(b1))

static __device__ __forceinline__ void cp16(uint32_t s, const void* g) {
    asm volatile("cp.async.cg.shared.global [%0], [%1], 16;" :: "r"(s), "l"(g));
}
#define CP_COMMIT() asm volatile("cp.async.commit_group;" ::: "memory")
#define CP_WAIT0()  asm volatile("cp.async.wait_group 0;" ::: "memory")

static __device__ __forceinline__ uint32_t redux_min(uint32_t v) {
    uint32_t d;
    asm volatile("redux.sync.min.u32 %0, %1, 0xFFFFFFFF;" : "=r"(d) : "r"(v));
    return d;
}
static __device__ __forceinline__ uint32_t fkey(float f) {
    const uint32_t u = __float_as_uint(f);
    return (u & 0x80000000u) ? ~u : (u | 0x80000000u);
}
static __device__ __forceinline__ float funkey(uint32_t k) {
    const uint32_t u = (k & 0x80000000u) ? (k ^ 0x80000000u) : ~k;
    return __uint_as_float(u);
}

// ---------------- W transpose + fp16 convert ----------------
__global__ void wsplit_kernel(const float* __restrict__ W0, const float* __restrict__ W1,
                              const float* __restrict__ W2, const float* __restrict__ W3)
{
    const int z = blockIdx.z;
    const float* W = (z == 0) ? W0 : (z == 1) ? W1 : (z == 2) ? W2 : W3;
    __shared__ float tile[32][33];
    const int tx = threadIdx.x, ty = threadIdx.y;
    const int k0 = blockIdx.x * 32, n0 = blockIdx.y * 32;
#pragma unroll
    for (int i = 0; i < 4; i++)
        tile[ty + 8 * i][tx] = W[(size_t)(k0 + ty + 8 * i) * 256 + n0 + tx];
    __syncthreads();
#pragma unroll
    for (int i = 0; i < 4; i++) {
        const float v = tile[tx][ty + 8 * i];
        g_wt[z][(size_t)(n0 + ty + 8 * i) * 768 + k0 + tx] = __float2half(v);
    }
}

// ---------------- A convert+store helper (fp32 -> fp16 hi/lo) ----------------
static __device__ __forceinline__ void store_a(char* st, const float4* aReg,
                                               int arow, int t)
{
#pragma unroll
    for (int p = 0; p < 8; p++) {
        const float4 v = aReg[p];
        const __half h0 = __float2half(v.x), h1 = __float2half(v.y);
        const __half h2 = __float2half(v.z), h3 = __float2half(v.w);
        const __half l0 = __float2half(v.x - __half2float(h0));
        const __half l1 = __float2half(v.y - __half2float(h1));
        const __half l2 = __float2half(v.z - __half2float(h2));
        const __half l3 = __float2half(v.w - __half2float(h3));
        __half2 hp0 = __halves2half2(h0, h1), hp1 = __halves2half2(h2, h3);
        __half2 lp0 = __halves2half2(l0, l1), lp1 = __halves2half2(l2, l3);
        uint2 hv, lv;
        hv.x = *(uint32_t*)&hp0; hv.y = *(uint32_t*)&hp1;
        lv.x = *(uint32_t*)&lp0; lv.y = *(uint32_t*)&lp1;
        const int byo = (p * 16 + arow) * ROWB + (t & 15) * 8;
        *(uint2*)(st + OFF_AH + byo) = hv;
        *(uint2*)(st + OFF_AL + byo) = lv;
    }
}

// ---------------- fused HMMA GEMM: C[m,256] = A[m,768] @ W + bias ----------
__global__ __launch_bounds__(256, 1)
void gemm_mma(const float* __restrict__ vf, const float* __restrict__ tf,
              const float* __restrict__ af,
              const float* __restrict__ bv, const float* __restrict__ bt,
              const float* __restrict__ bp, const float* __restrict__ ba,
              float* __restrict__ out)
{
    extern __shared__ char dynsm[];
    __shared__ int sRowOff[128];

    const int t = threadIdx.x;
    const int warp = t >> 5;
    const int lane = t & 31;
    const int m0 = blockIdx.x * 128;
    const int bn = blockIdx.y;           // 0 or 1 (N halves)

    const int seg = (m0 < SEG1) ? 0 : (m0 < SEG2) ? 1 : (m0 < SEG3) ? 2 : 3;
    const float* Abase = (seg == 0 || seg == 2) ? vf : (seg == 1 ? tf : af);
    const float* bias = (seg == 0) ? bv : (seg == 1) ? bt : (seg == 2) ? bp : ba;
    const __half* wt = g_wt[seg];

    float* dstbase;
    int mrel;
    if (seg == 0)      { dstbase = out;            mrel = m0; }
    else if (seg == 1) { dstbase = out + Bb * EE;  mrel = m0 - SEG1; }
    else if (seg == 2) { dstbase = g_pat;          mrel = m0 - SEG2; }
    else               { dstbase = g_att;          mrel = m0 - SEG3; }

    // row source offsets (floats)
    if (t < 128) {
        const int m = m0 + t;
        int off;
        if (m < SEG1)        off = m * (193 * 768);
        else if (m < SEG2)   off = (m - SEG1) * 768;
        else if (m < SEG3) { const int mm = m - SEG2;
                             off = ((mm / 192) * 193 + 1 + (mm % 192)) * 768; }
        else                 off = (m - SEG3) * 768;
        sRowOff[t] = off;
    }
    __syncthreads();

    const uint32_t smem_u = smem_u32(dynsm);
    const int warp_m = warp & 1;          // 2 m-warps (64 rows each)
    const int warp_n = warp >> 1;         // 4 n-warps (32 cols each)
    const int g = lane >> 3, lr = lane & 7;
    const uint32_t aoff = (uint32_t)((warp_m * 64 + (g & 1) * 8 + lr) * ROWB + (g >> 1) * 16);
    const uint32_t boff = (uint32_t)((warp_n * 32 + (g & 1) * 8 + lr) * ROWB + (g >> 1) * 16);

    // A-loader mapping: 8 passes, each thread one float4 (128 rows x 64 floats)
    const int arow = t >> 4;              // 0..15, + 16*pass
    const int acol = (t & 15) * 4;        // floats
    // B-loader mapping: 4 passes of cp16 (128 rows x 128 bytes)
    const int brow = t >> 3;              // 0..31, + 32*pass
    const int bseg = (t & 7) * 16;        // bytes within 128B row

    float acc[4][4][4] = {};
    float4 aReg[8];

    // ---- prologue: stage 0 ----
#pragma unroll
    for (int p = 0; p < 8; p++)
        aReg[p] = *(const float4*)(Abase + sRowOff[p * 16 + arow] + acol);
#pragma unroll
    for (int q = 0; q < 4; q++) {
        const int row = brow + q * 32;
        const size_t gb = (size_t)(bn * 128 + row) * 1536 + bseg;
        const uint32_t sb = smem_u + (uint32_t)(row * ROWB + bseg);
        cp16(sb + OFF_B, (const char*)wt + gb);
    }
    CP_COMMIT();
    store_a(dynsm, aReg, arow, t);
    CP_WAIT0();
    __syncthreads();

    // ---- main loop ----
    for (int c = 0; c < NCH; c++) {
        const int cur = c & 1;
        const int nxt = cur ^ 1;
        if (c + 1 < NCH) {
            const int kc = (c + 1) * BKC;
#pragma unroll
            for (int p = 0; p < 8; p++)
                aReg[p] = *(const float4*)(Abase + sRowOff[p * 16 + arow] + kc + acol);
            const uint32_t stb = smem_u + nxt * STAGESZ;
#pragma unroll
            for (int q = 0; q < 4; q++) {
                const int row = brow + q * 32;
                const size_t gb = (size_t)(bn * 128 + row) * 1536 + kc * 2 + bseg;
                cp16(stb + (uint32_t)(row * ROWB + bseg) + OFF_B, (const char*)wt + gb);
            }
            CP_COMMIT();
        }

        // compute on cur
        const uint32_t sb = smem_u + cur * STAGESZ;
#pragma unroll
        for (int ks = 0; ks < 4; ks++) {
            uint32_t ah[4][4], al[4][4], bb[2][4];
#pragma unroll
            for (int mt = 0; mt < 4; mt++) {
                LDSM4(ah[mt], sb + OFF_AH + aoff + mt * (16 * ROWB) + ks * 32);
                LDSM4(al[mt], sb + OFF_AL + aoff + mt * (16 * ROWB) + ks * 32);
            }
#pragma unroll
            for (int n2 = 0; n2 < 2; n2++)
                LDSM4(bb[n2], sb + OFF_B + boff + n2 * (16 * ROWB) + ks * 32);
#pragma unroll
            for (int mt = 0; mt < 4; mt++)
#pragma unroll
                for (int nt = 0; nt < 4; nt++) {
                    float* cc = acc[mt][nt];
                    const int n2 = nt >> 1, no = nt & 1;
                    MMA(cc, ah[mt], bb[n2][no], bb[n2][2 + no]);
                    MMA(cc, al[mt], bb[n2][no], bb[n2][2 + no]);
                }
        }

        if (c + 1 < NCH) {
            store_a(dynsm + nxt * STAGESZ, aReg, arow, t);
            CP_WAIT0();
        }
        __syncthreads();
    }

    // ---- epilogue: bias add + store ----
    const int r0 = lane >> 2;
    const int cp2 = (lane & 3) * 2;
#pragma unroll
    for (int nt = 0; nt < 4; nt++) {
        const int gcol = bn * 128 + warp_n * 32 + nt * 8 + cp2;
        const float2 bb = *(const float2*)(bias + gcol);
#pragma unroll
        for (int mt = 0; mt < 4; mt++) {
            const int row0 = mrel + warp_m * 64 + mt * 16 + r0;
            float2 v0, v1;
            v0.x = acc[mt][nt][0] + bb.x; v0.y = acc[mt][nt][1] + bb.y;
            v1.x = acc[mt][nt][2] + bb.x; v1.y = acc[mt][nt][3] + bb.y;
            *(float2*)(dstbase + (size_t)row0 * EE + gcol) = v0;
            *(float2*)(dstbase + (size_t)(row0 + 8) * EE + gcol) = v1;
        }
    }
}

// ---------------- sim v2: full pat tile in SMEM, fused normalization -------
#define PATPITCH 257
__global__ __launch_bounds__(256)
void sim_kernel(const float* __restrict__ pat, const float* __restrict__ att,
                float* __restrict__ sim)
{
    extern __shared__ float pat_s[];              // [192][257]
    __shared__ float inv_s[Pp];
    const int b = blockIdx.x;
    const int t = threadIdx.x;
    const int warp = t >> 5, lane = t & 31;

    const float* pb = pat + (size_t)b * Pp * EE;
#pragma unroll
    for (int i = 0; i < Pp; i++)
        pat_s[i * PATPITCH + t] = pb[i * EE + t];

    // att row 'warp' -> registers, normalized
    float a[8];
    {
        const float* ar = att + ((size_t)b * AA + warp) * EE;
        float ss = 0.f;
#pragma unroll
        for (int i = 0; i < 8; i++) { a[i] = ar[lane + 32 * i]; ss += a[i] * a[i]; }
#pragma unroll
        for (int o = 16; o; o >>= 1) ss += __shfl_xor_sync(0xffffffffu, ss, o);
        const float inv = 1.f / fmaxf(sqrtf(ss), 1e-12f);
#pragma unroll
        for (int i = 0; i < 8; i++) a[i] *= inv;
    }
    __syncthreads();

    if (t < Pp) {
        const float* pr = pat_s + t * PATPITCH;
        float ss = 0.f;
#pragma unroll 8
        for (int e = 0; e < EE; e++) ss += pr[e] * pr[e];
        inv_s[t] = 1.f / fmaxf(sqrtf(ss), 1e-12f);
    }
    __syncthreads();

    float* srow = sim + ((size_t)b * AA + warp) * Pp;
    for (int p = 0; p < Pp; p++) {
        const float* pr = pat_s + p * PATPITCH + lane;
        float acc = 0.f;
#pragma unroll
        for (int i = 0; i < 8; i++) acc += a[i] * pr[32 * i];
#pragma unroll
        for (int o = 16; o; o >>= 1) acc += __shfl_xor_sync(0xffffffffu, acc, o);
        if (lane == 0) srow[p] = acc * inv_s[p];
    }
}

// ---------------- Hungarian v3: register JV + redux.sync min ----------------
#define HW 4
__global__ __launch_bounds__(32 * HW)
void hungarian_kernel(const float* __restrict__ simg, float* __restrict__ out)
{
    __shared__ float cost_s[HW][AA][Pp];
    __shared__ float u_s[HW][AA + 1];
    __shared__ int   p_s[HW][Pp + 1];
    __shared__ short way_s[HW][Pp + 1];

    const int w = threadIdx.x >> 5;
    const int lane = threadIdx.x & 31;
    const int b = blockIdx.x * HW + w;
    const float FINF = 1e30f;

    float (*cost)[Pp] = cost_s[w];
    float* u = u_s[w];
    int*   p = p_s[w];
    short* way = way_s[w];

    for (int idx = lane; idx < AA * Pp; idx += 32)
        cost[idx / Pp][idx % Pp] = -simg[(size_t)b * AA * Pp + idx];

    float total = 0.f;

    for (int round = 0; round < KK; round++) {
        float v[6];
#pragma unroll
        for (int s = 0; s < 6; s++) v[s] = 0.f;
        for (int j = lane; j <= Pp; j += 32) p[j] = 0;
        if (lane < AA + 1) u[lane] = 0.f;
        __syncwarp();

        for (int i = 1; i <= AA; i++) {
            if (lane == 0) p[0] = i;
            float minv[6];
            unsigned usedm = 0;
#pragma unroll
            for (int s = 0; s < 6; s++) minv[s] = FINF;
            __syncwarp();

            int j0 = 0;
            bool used0 = false;
            while (true) {
                if (j0 == 0) used0 = true;
                else {
                    const int cidx = j0 - 1;
                    if ((cidx & 31) == lane) usedm |= 1u << (cidx >> 5);
                }
                const int i0 = p[j0];
                const float ui0 = u[i0];
                const float* crow = cost[i0 - 1];

                float best = FINF;
                int bestj = 1 << 20;
#pragma unroll
                for (int s = 0; s < 6; s++) {
                    if (!((usedm >> s) & 1)) {
                        const int c = s * 32 + lane;
                        const float cur = crow[c] - ui0 - v[s];
                        if (cur < minv[s]) { minv[s] = cur; way[c + 1] = (short)j0; }
                        const float mv = minv[s];
                        if (mv < best) { best = mv; bestj = c + 1; }
                    }
                }
                // global min via redux (value, then smallest index among ties)
                const uint32_t mykey = fkey(best);
                const uint32_t gkey = redux_min(mykey);
                const uint32_t idxc = (mykey == gkey) ? (uint32_t)bestj : 0xFFFFFFFFu;
                const int j1 = (int)redux_min(idxc);
                const float delta = funkey(gkey);

                if (used0 && lane == 0) u[p[0]] += delta;
#pragma unroll
                for (int s = 0; s < 6; s++) {
                    if ((usedm >> s) & 1) {
                        const int j = s * 32 + lane + 1;
                        v[s] -= delta;
                        u[p[j]] += delta;
                    } else {
                        minv[s] -= delta;
                    }
                }
                __syncwarp();
                j0 = j1;
                if (p[j0] == 0) break;
            }
            __syncwarp();
            if (lane == 0) {
                int jc = j0;
                while (jc) { const int jn = way[jc]; p[jc] = p[jn]; jc = jn; }
            }
            __syncwarp();
        }

        // collect matched values + mask
#pragma unroll
        for (int s = 0; s < 6; s++) {
            const int c = s * 32 + lane;
            const int r = p[c + 1];
            if (r) {
                total += -cost[r - 1][c];
                cost[r - 1][c] = 100.f;
            }
        }
        __syncwarp();
    }

#pragma unroll
    for (int o = 16; o; o >>= 1) total += __shfl_xor_sync(0xffffffffu, total, o);
    if (lane == 0) out[b] = total * (1.f / (KK * AA));
}

// ---------------- launch ----------------
extern "C" void kernel_launch(void* const* d_in, const int* in_sizes, int n_in,
                              void* d_out, int out_size)
{
    const float* vf = (const float*)d_in[0];
    const float* tf = (const float*)d_in[1];
    const float* af = (const float*)d_in[2];
    const float* Wv = (const float*)d_in[4];
    const float* bv = (const float*)d_in[5];
    const float* Wt = (const float*)d_in[6];
    const float* bt = (const float*)d_in[7];
    const float* Wp = (const float*)d_in[8];
    const float* bp = (const float*)d_in[9];
    const float* Wa = (const float*)d_in[10];
    const float* ba = (const float*)d_in[11];

    float* out = (float*)d_out;
    float* ls = out + 2 * Bb * EE;

    float *gpat, *gatt, *gsim;
    cudaGetSymbolAddress((void**)&gpat, g_pat);
    cudaGetSymbolAddress((void**)&gatt, g_att);
    cudaGetSymbolAddress((void**)&gsim, g_sim);

    cudaFuncSetAttribute(gemm_mma, cudaFuncAttributeMaxDynamicSharedMemorySize, DYNSZ);
    cudaFuncSetAttribute(sim_kernel, cudaFuncAttributeMaxDynamicSharedMemorySize,
                         Pp * PATPITCH * 4);

    wsplit_kernel<<<dim3(24, 8, 4), dim3(32, 8)>>>(Wv, Wt, Wp, Wa);
    gemm_mma<<<dim3(MTILES, 2), 256, DYNSZ>>>(vf, tf, af, bv, bt, bp, ba, out);
    sim_kernel<<<Bb, 256, Pp * PATPITCH * 4>>>(gpat, gatt, gsim);
    hungarian_kernel<<<Bb / HW, 32 * HW>>>(gsim, ls);
}

// round 6
// speedup vs baseline: 4.3444x; 1.3289x over previous
#include <cuda_runtime.h>
#include <cuda_bf16.h>
#include <cuda_fp16.h>
#include <cstdint>

// ---------------- constants ----------------
#define Bb   256
#define Pp   192
#define DD   768
#define EE   256
#define AA   8
#define KK   4

#define M_TOTAL   51712          // 256(ve) + 256(te) + 49152(pat) + 2048(att)
#define SEG1      256
#define SEG2      512
#define SEG3      49664
#define MTILES    404            // M_TOTAL / 128
#define BKC       64             // K per chunk (fp16 elems)
#define NCH       12             // 768 / 64

// SMEM: 2 operands (A, B), each 128 rows x 144 bytes, double buffered
#define ROWB    144
#define OPSZ    (128 * ROWB)     // 18432
#define OFF_A   0
#define OFF_B   (OPSZ)
#define STAGESZ (2 * OPSZ)       // 36864
#define DYNSZ   (2 * STAGESZ)    // 73728

// ---------------- scratch ----------------
__device__ float g_pat[(size_t)Bb * Pp * EE];   // unnormalized patch embed
__device__ float g_att[(size_t)Bb * AA * EE];   // unnormalized att embed
__device__ float g_sim[(size_t)Bb * AA * Pp];
__device__ __half g_wt[4][256 * 768];           // W^T fp16, [N][K]

// ---------------- PTX helpers ----------------
static __device__ __forceinline__ uint32_t smem_u32(const void* p) {
    uint32_t a;
    asm("{ .reg .u64 t; cvta.to.shared.u64 t, %1; cvt.u32.u64 %0, t; }"
        : "=r"(a) : "l"(p));
    return a;
}

#define LDSM4(r, addr) \
    asm volatile("ldmatrix.sync.aligned.m8n8.x4.shared.b16 {%0,%1,%2,%3}, [%4];" \
        : "=r"((r)[0]), "=r"((r)[1]), "=r"((r)[2]), "=r"((r)[3]) : "r"(addr))

#define MMA(c, a, b0, b1) \
    asm volatile("mma.sync.aligned.m16n8k16.row.col.f32.f16.f16.f32 " \
        "{%0,%1,%2,%3}, {%4,%5,%6,%7}, {%8,%9}, {%0,%1,%2,%3};" \
        : "+f"((c)[0]), "+f"((c)[1]), "+f"((c)[2]), "+f"((c)[3]) \
        : "r"((a)[0]), "r"((a)[1]), "r"((a)[2]), "r"((a)[3]), "r"(b0), "r"(b1))

static __device__ __forceinline__ void cp16(uint32_t s, const void* g) {
    asm volatile("cp.async.cg.shared.global [%0], [%1], 16;" :: "r"(s), "l"(g));
}
#define CP_COMMIT() asm volatile("cp.async.commit_group;" ::: "memory")
#define CP_WAIT0()  asm volatile("cp.async.wait_group 0;" ::: "memory")

static __device__ __forceinline__ uint32_t redux_min(uint32_t v) {
    uint32_t d;
    asm volatile("redux.sync.min.u32 %0, %1, 0xFFFFFFFF;" : "=r"(d) : "r"(v));
    return d;
}
static __device__ __forceinline__ uint32_t fkey(float f) {
    const uint32_t u = __float_as_uint(f);
    return (u & 0x80000000u) ? ~u : (u | 0x80000000u);
}
static __device__ __forceinline__ float funkey(uint32_t k) {
    const uint32_t u = (k & 0x80000000u) ? (k ^ 0x80000000u) : ~k;
    return __uint_as_float(u);
}

// ---------------- W transpose + fp16 convert ----------------
__global__ void wsplit_kernel(const float* __restrict__ W0, const float* __restrict__ W1,
                              const float* __restrict__ W2, const float* __restrict__ W3)
{
    const int z = blockIdx.z;
    const float* W = (z == 0) ? W0 : (z == 1) ? W1 : (z == 2) ? W2 : W3;
    __shared__ float tile[32][33];
    const int tx = threadIdx.x, ty = threadIdx.y;
    const int k0 = blockIdx.x * 32, n0 = blockIdx.y * 32;
#pragma unroll
    for (int i = 0; i < 4; i++)
        tile[ty + 8 * i][tx] = W[(size_t)(k0 + ty + 8 * i) * 256 + n0 + tx];
    __syncthreads();
#pragma unroll
    for (int i = 0; i < 4; i++) {
        const float v = tile[tx][ty + 8 * i];
        g_wt[z][(size_t)(n0 + ty + 8 * i) * 768 + k0 + tx] = __float2half(v);
    }
}

// ---------------- A convert+store helper (fp32 -> fp16) ----------------
static __device__ __forceinline__ void store_a(char* st, const float4* aReg,
                                               int arow, int t)
{
#pragma unroll
    for (int p = 0; p < 8; p++) {
        const float4 v = aReg[p];
        __half2 hp0 = __floats2half2_rn(v.x, v.y);
        __half2 hp1 = __floats2half2_rn(v.z, v.w);
        uint2 hv;
        hv.x = *(uint32_t*)&hp0; hv.y = *(uint32_t*)&hp1;
        const int byo = (p * 16 + arow) * ROWB + (t & 15) * 8;
        *(uint2*)(st + OFF_A + byo) = hv;
    }
}

// ---------------- fused HMMA GEMM: C[m,256] = A[m,768] @ W + bias ----------
__global__ __launch_bounds__(256, 1)
void gemm_mma(const float* __restrict__ vf, const float* __restrict__ tf,
              const float* __restrict__ af,
              const float* __restrict__ bv, const float* __restrict__ bt,
              const float* __restrict__ bp, const float* __restrict__ ba,
              float* __restrict__ out)
{
    extern __shared__ char dynsm[];
    __shared__ int sRowOff[128];

    const int t = threadIdx.x;
    const int warp = t >> 5;
    const int lane = t & 31;
    const int m0 = blockIdx.y * 128;
    const int bn = blockIdx.x;           // 0 or 1 (N halves) — adjacent CTAs share A via L2

    const int seg = (m0 < SEG1) ? 0 : (m0 < SEG2) ? 1 : (m0 < SEG3) ? 2 : 3;
    const float* Abase = (seg == 0 || seg == 2) ? vf : (seg == 1 ? tf : af);
    const float* bias = (seg == 0) ? bv : (seg == 1) ? bt : (seg == 2) ? bp : ba;
    const __half* wt = g_wt[seg];

    float* dstbase;
    int mrel;
    if (seg == 0)      { dstbase = out;            mrel = m0; }
    else if (seg == 1) { dstbase = out + Bb * EE;  mrel = m0 - SEG1; }
    else if (seg == 2) { dstbase = g_pat;          mrel = m0 - SEG2; }
    else               { dstbase = g_att;          mrel = m0 - SEG3; }

    // row source offsets (floats)
    if (t < 128) {
        const int m = m0 + t;
        int off;
        if (m < SEG1)        off = m * (193 * 768);
        else if (m < SEG2)   off = (m - SEG1) * 768;
        else if (m < SEG3) { const int mm = m - SEG2;
                             off = ((mm / 192) * 193 + 1 + (mm % 192)) * 768; }
        else                 off = (m - SEG3) * 768;
        sRowOff[t] = off;
    }
    __syncthreads();

    const uint32_t smem_u = smem_u32(dynsm);
    const int warp_m = warp & 1;          // 2 m-warps (64 rows each)
    const int warp_n = warp >> 1;         // 4 n-warps (32 cols each)
    const int g = lane >> 3, lr = lane & 7;
    const uint32_t aoff = (uint32_t)((warp_m * 64 + (g & 1) * 8 + lr) * ROWB + (g >> 1) * 16);
    const uint32_t boff = (uint32_t)((warp_n * 32 + (g & 1) * 8 + lr) * ROWB + (g >> 1) * 16);

    // A-loader mapping: 8 passes, each thread one float4 (128 rows x 64 floats)
    const int arow = t >> 4;              // 0..15, + 16*pass
    const int acol = (t & 15) * 4;        // floats
    // B-loader mapping: 4 passes of cp16 (128 rows x 128 bytes)
    const int brow = t >> 3;              // 0..31, + 32*pass
    const int bseg = (t & 7) * 16;        // bytes within 128B row

    float acc[4][4][4] = {};
    float4 aReg[8];

    // ---- prologue: stage 0 ----
#pragma unroll
    for (int p = 0; p < 8; p++)
        aReg[p] = *(const float4*)(Abase + sRowOff[p * 16 + arow] + acol);
#pragma unroll
    for (int q = 0; q < 4; q++) {
        const int row = brow + q * 32;
        const size_t gb = (size_t)(bn * 128 + row) * 1536 + bseg;
        cp16(smem_u + (uint32_t)(row * ROWB + bseg) + OFF_B, (const char*)wt + gb);
    }
    CP_COMMIT();
    store_a(dynsm, aReg, arow, t);
    CP_WAIT0();
    __syncthreads();

    // ---- main loop ----
    for (int c = 0; c < NCH; c++) {
        const int cur = c & 1;
        const int nxt = cur ^ 1;
        if (c + 1 < NCH) {
            const int kc = (c + 1) * BKC;
#pragma unroll
            for (int p = 0; p < 8; p++)
                aReg[p] = *(const float4*)(Abase + sRowOff[p * 16 + arow] + kc + acol);
            const uint32_t stb = smem_u + nxt * STAGESZ;
#pragma unroll
            for (int q = 0; q < 4; q++) {
                const int row = brow + q * 32;
                const size_t gb = (size_t)(bn * 128 + row) * 1536 + kc * 2 + bseg;
                cp16(stb + (uint32_t)(row * ROWB + bseg) + OFF_B, (const char*)wt + gb);
            }
            CP_COMMIT();
        }

        // compute on cur
        const uint32_t sb = smem_u + cur * STAGESZ;
#pragma unroll
        for (int ks = 0; ks < 4; ks++) {
            uint32_t ah[4][4], bb[2][4];
#pragma unroll
            for (int mt = 0; mt < 4; mt++)
                LDSM4(ah[mt], sb + OFF_A + aoff + mt * (16 * ROWB) + ks * 32);
#pragma unroll
            for (int n2 = 0; n2 < 2; n2++)
                LDSM4(bb[n2], sb + OFF_B + boff + n2 * (16 * ROWB) + ks * 32);
#pragma unroll
            for (int mt = 0; mt < 4; mt++)
#pragma unroll
                for (int nt = 0; nt < 4; nt++) {
                    float* cc = acc[mt][nt];
                    const int n2 = nt >> 1, no = nt & 1;
                    MMA(cc, ah[mt], bb[n2][no], bb[n2][2 + no]);
                }
        }

        if (c + 1 < NCH) {
            store_a(dynsm + nxt * STAGESZ, aReg, arow, t);
            CP_WAIT0();
        }
        __syncthreads();
    }

    // ---- epilogue: bias add + store ----
    const int r0 = lane >> 2;
    const int cp2 = (lane & 3) * 2;
#pragma unroll
    for (int nt = 0; nt < 4; nt++) {
        const int gcol = bn * 128 + warp_n * 32 + nt * 8 + cp2;
        const float2 bb = *(const float2*)(bias + gcol);
#pragma unroll
        for (int mt = 0; mt < 4; mt++) {
            const int row0 = mrel + warp_m * 64 + mt * 16 + r0;
            float2 v0, v1;
            v0.x = acc[mt][nt][0] + bb.x; v0.y = acc[mt][nt][1] + bb.y;
            v1.x = acc[mt][nt][2] + bb.x; v1.y = acc[mt][nt][3] + bb.y;
            *(float2*)(dstbase + (size_t)row0 * EE + gcol) = v0;
            *(float2*)(dstbase + (size_t)(row0 + 8) * EE + gcol) = v1;
        }
    }
}

// ---------------- sim v2: full pat tile in SMEM, fused normalization -------
#define PATPITCH 257
__global__ __launch_bounds__(256)
void sim_kernel(const float* __restrict__ pat, const float* __restrict__ att,
                float* __restrict__ sim)
{
    extern __shared__ float pat_s[];              // [192][257]
    __shared__ float inv_s[Pp];
    const int b = blockIdx.x;
    const int t = threadIdx.x;
    const int warp = t >> 5, lane = t & 31;

    const float* pb = pat + (size_t)b * Pp * EE;
#pragma unroll
    for (int i = 0; i < Pp; i++)
        pat_s[i * PATPITCH + t] = pb[i * EE + t];

    // att row 'warp' -> registers, normalized
    float a[8];
    {
        const float* ar = att + ((size_t)b * AA + warp) * EE;
        float ss = 0.f;
#pragma unroll
        for (int i = 0; i < 8; i++) { a[i] = ar[lane + 32 * i]; ss += a[i] * a[i]; }
#pragma unroll
        for (int o = 16; o; o >>= 1) ss += __shfl_xor_sync(0xffffffffu, ss, o);
        const float inv = 1.f / fmaxf(sqrtf(ss), 1e-12f);
#pragma unroll
        for (int i = 0; i < 8; i++) a[i] *= inv;
    }
    __syncthreads();

    if (t < Pp) {
        const float* pr = pat_s + t * PATPITCH;
        float ss = 0.f;
#pragma unroll 8
        for (int e = 0; e < EE; e++) ss += pr[e] * pr[e];
        inv_s[t] = 1.f / fmaxf(sqrtf(ss), 1e-12f);
    }
    __syncthreads();

    float* srow = sim + ((size_t)b * AA + warp) * Pp;
    for (int p = 0; p < Pp; p++) {
        const float* pr = pat_s + p * PATPITCH + lane;
        float acc = 0.f;
#pragma unroll
        for (int i = 0; i < 8; i++) acc += a[i] * pr[32 * i];
#pragma unroll
        for (int o = 16; o; o >>= 1) acc += __shfl_xor_sync(0xffffffffu, acc, o);
        if (lane == 0) srow[p] = acc * inv_s[p];
    }
}

// ---------------- Hungarian v3: register JV + redux.sync min ----------------
#define HW 4
__global__ __launch_bounds__(32 * HW)
void hungarian_kernel(const float* __restrict__ simg, float* __restrict__ out)
{
    __shared__ float cost_s[HW][AA][Pp];
    __shared__ float u_s[HW][AA + 1];
    __shared__ int   p_s[HW][Pp + 1];
    __shared__ short way_s[HW][Pp + 1];

    const int w = threadIdx.x >> 5;
    const int lane = threadIdx.x & 31;
    const int b = blockIdx.x * HW + w;
    const float FINF = 1e30f;

    float (*cost)[Pp] = cost_s[w];
    float* u = u_s[w];
    int*   p = p_s[w];
    short* way = way_s[w];

    for (int idx = lane; idx < AA * Pp; idx += 32)
        cost[idx / Pp][idx % Pp] = -simg[(size_t)b * AA * Pp + idx];

    float total = 0.f;

    for (int round = 0; round < KK; round++) {
        float v[6];
#pragma unroll
        for (int s = 0; s < 6; s++) v[s] = 0.f;
        for (int j = lane; j <= Pp; j += 32) p[j] = 0;
        if (lane < AA + 1) u[lane] = 0.f;
        __syncwarp();

        for (int i = 1; i <= AA; i++) {
            if (lane == 0) p[0] = i;
            float minv[6];
            unsigned usedm = 0;
#pragma unroll
            for (int s = 0; s < 6; s++) minv[s] = FINF;
            __syncwarp();

            int j0 = 0;
            bool used0 = false;
            while (true) {
                if (j0 == 0) used0 = true;
                else {
                    const int cidx = j0 - 1;
                    if ((cidx & 31) == lane) usedm |= 1u << (cidx >> 5);
                }
                const int i0 = p[j0];
                const float ui0 = u[i0];
                const float* crow = cost[i0 - 1];

                float best = FINF;
                int bestj = 1 << 20;
#pragma unroll
                for (int s = 0; s < 6; s++) {
                    if (!((usedm >> s) & 1)) {
                        const int c = s * 32 + lane;
                        const float cur = crow[c] - ui0 - v[s];
                        if (cur < minv[s]) { minv[s] = cur; way[c + 1] = (short)j0; }
                        const float mv = minv[s];
                        if (mv < best) { best = mv; bestj = c + 1; }
                    }
                }
                // global min via redux (value, then smallest index among ties)
                const uint32_t mykey = fkey(best);
                const uint32_t gkey = redux_min(mykey);
                const uint32_t idxc = (mykey == gkey) ? (uint32_t)bestj : 0xFFFFFFFFu;
                const int j1 = (int)redux_min(idxc);
                const float delta = funkey(gkey);

                if (used0 && lane == 0) u[p[0]] += delta;
#pragma unroll
                for (int s = 0; s < 6; s++) {
                    if ((usedm >> s) & 1) {
                        const int j = s * 32 + lane + 1;
                        v[s] -= delta;
                        u[p[j]] += delta;
                    } else {
                        minv[s] -= delta;
                    }
                }
                __syncwarp();
                j0 = j1;
                if (p[j0] == 0) break;
            }
            __syncwarp();
            if (lane == 0) {
                int jc = j0;
                while (jc) { const int jn = way[jc]; p[jc] = p[jn]; jc = jn; }
            }
            __syncwarp();
        }

        // collect matched values + mask
#pragma unroll
        for (int s = 0; s < 6; s++) {
            const int c = s * 32 + lane;
            const int r = p[c + 1];
            if (r) {
                total += -cost[r - 1][c];
                cost[r - 1][c] = 100.f;
            }
        }
        __syncwarp();
    }

#pragma unroll
    for (int o = 16; o; o >>= 1) total += __shfl_xor_sync(0xffffffffu, total, o);
    if (lane == 0) out[b] = total * (1.f / (KK * AA));
}

// ---------------- launch ----------------
extern "C" void kernel_launch(void* const* d_in, const int* in_sizes, int n_in,
                              void* d_out, int out_size)
{
    const float* vf = (const float*)d_in[0];
    const float* tf = (const float*)d_in[1];
    const float* af = (const float*)d_in[2];
    const float* Wv = (const float*)d_in[4];
    const float* bv = (const float*)d_in[5];
    const float* Wt = (const float*)d_in[6];
    const float* bt = (const float*)d_in[7];
    const float* Wp = (const float*)d_in[8];
    const float* bp = (const float*)d_in[9];
    const float* Wa = (const float*)d_in[10];
    const float* ba = (const float*)d_in[11];

    float* out = (float*)d_out;
    float* ls = out + 2 * Bb * EE;

    float *gpat, *gatt, *gsim;
    cudaGetSymbolAddress((void**)&gpat, g_pat);
    cudaGetSymbolAddress((void**)&gatt, g_att);
    cudaGetSymbolAddress((void**)&gsim, g_sim);

    cudaFuncSetAttribute(gemm_mma, cudaFuncAttributeMaxDynamicSharedMemorySize, DYNSZ);
    cudaFuncSetAttribute(sim_kernel, cudaFuncAttributeMaxDynamicSharedMemorySize,
                         Pp * PATPITCH * 4);

    wsplit_kernel<<<dim3(24, 8, 4), dim3(32, 8)>>>(Wv, Wt, Wp, Wa);
    gemm_mma<<<dim3(2, MTILES), 256, DYNSZ>>>(vf, tf, af, bv, bt, bp, ba, out);
    sim_kernel<<<Bb, 256, Pp * PATPITCH * 4>>>(gpat, gatt, gsim);
    hungarian_kernel<<<Bb / HW, 32 * HW>>>(gsim, ls);
}